// round 11
// baseline (speedup 1.0000x reference)
#include <cuda_runtime.h>
#include <stdint.h>

// FP32 bit-pulse -> FP8 E4M3 bit-pulse converter — FINAL.
// Input : N*32 floats (0.0f/1.0f), row = [S, E7..E0, M22..M0] MSB first
// Output: N*8  floats, row = [S, E3..E0, M2..M0]
//
// Warp-cooperative smem nibble transpose (best-measured R5 config):
//  - warp owns 32 consecutive rows (4KB contiguous input)
//  - 8 coalesced LDG.128 (__ldcs) passes; each lane reduces its uint4 to a
//    4-bit nibble (bit 29 of 1.0f) byte-stored at smem[p*32+lane] (row-major
//    nibble order by construction)
//  - lane r reads its row's 8 nibble-bytes with one conflict-free LDS.64,
//    packs into the IEEE754 word, converts (bit-exact RNE E4M3), stores
//    2x STG.128 (__stcs)
//  - output floats built as bit*0x3F800000 (one IMAD each) instead of I2F:
//    shorter serial chain into the stores, fewer instructions.
//
// Measured across 8 structural/cache/scheduling variants: harness steady
// state is pinned at 51.2-51.9us = 320MB irreducible traffic at ~6.3TB/s
// sustained HBM + fixed replay overhead. DRAM 80-85%, all other pipes <=33%.
// This kernel is at the mixed-stream HBM floor.

__device__ __forceinline__ float bitf(uint32_t w, int b)
{
    // ((w >> b) & 1) ? 1.0f : 0.0f  as a single-mul bit select
    return __uint_as_float(((w >> b) & 1u) * 0x3F800000u);
}

__device__ __forceinline__ void convert_row(uint32_t packed,
                                            float4& o0, float4& o1)
{
    uint32_t exp  = (packed >> 23) & 0xFFu;
    uint32_t mant = packed & 0x7FFFFFu;

    // normal path: RNE round 23 -> 3 mantissa bits
    uint32_t kept = mant >> 20;
    uint32_t R    = (mant >> 19) & 1u;
    uint32_t S    = (mant & ((1u << 19) - 1u)) != 0u;
    uint32_t L    = kept & 1u;
    uint32_t mr   = kept + (R & (S | L));
    uint32_t carry = mr >> 3;
    uint32_t mant_norm = carry ? 0u : (mr & 7u);
    uint32_t exp_norm  = exp - 120u + carry;

    // subnormal path (117 <= exp <= 120)
    uint32_t full = (1u << 23) | mant;
    int shi = 141 - (int)exp;
    if (shi < 1)  shi = 1;
    if (shi > 24) shi = 24;
    uint32_t sh = (uint32_t)shi;
    uint32_t kept_s = full >> sh;
    uint32_t Rs = (full >> (sh - 1u)) & 1u;
    uint32_t Ss = (full & ((1u << (sh - 1u)) - 1u)) != 0u;
    uint32_t Ls = kept_s & 1u;
    uint32_t ms = kept_s + (Rs & (Ss | Ls));
    uint32_t sub_exp  = (ms >= 8u) ? 1u : 0u;
    uint32_t sub_mant = (ms >= 8u) ? 0u : ms;

    uint32_t exp8, mant8;
    if (exp > 134u)                      { exp8 = 15u;      mant8 = 6u;        }
    else if (exp >= 117u && exp <= 120u) { exp8 = sub_exp;  mant8 = sub_mant;  }
    else if (exp < 117u)                 { exp8 = 0u;       mant8 = 0u;        }
    else                                 { exp8 = exp_norm; mant8 = mant_norm; }

    o0.x = bitf(packed, 31);   // sign
    o0.y = bitf(exp8, 3);
    o0.z = bitf(exp8, 2);
    o0.w = bitf(exp8, 1);
    o1.x = bitf(exp8, 0);
    o1.y = bitf(mant8, 2);
    o1.z = bitf(mant8, 1);
    o1.w = bitf(mant8, 0);
}

__device__ __forceinline__ uint32_t nibble_of(uint4 v)
{
    return (((v.x >> 29) & 1u) << 3)
         | (((v.y >> 29) & 1u) << 2)
         | (((v.z >> 29) & 1u) << 1)
         |  ((v.w >> 29) & 1u);
}

__global__ __launch_bounds__(256) void fp32_to_fp8_pulse_kernel(
    const uint4* __restrict__ in,   // 8 x uint4 per row
    float4* __restrict__ out,       // 2 x float4 per row
    int nrows)
{
    __shared__ uint8_t snib[8][256];   // per-warp: 32 rows x 8 nibble-bytes

    const int warp = threadIdx.x >> 5;
    const int lane = threadIdx.x & 31;
    const int baserow = (blockIdx.x * 8 + warp) * 32;
    if (baserow >= nrows) return;

    if (baserow + 32 <= nrows) {
        // ---- fast path: full 32-row tile ----
        const uint4* tile = in + (size_t)baserow * 8;

        // coalesced streaming loads; each lane stores one nibble-byte per pass.
#pragma unroll
        for (int p = 0; p < 8; p++) {
            uint4 v = __ldcs(&tile[p * 32 + lane]);
            snib[warp][p * 32 + lane] = (uint8_t)nibble_of(v);
        }
        __syncwarp();

        // lane r: one LDS.64 fetches row r's 8 nibbles (bytes 8r..8r+7)
        uint2 u = *reinterpret_cast<const uint2*>(&snib[warp][lane * 8]);

        uint32_t hi = ((u.x & 0x0000000Fu) << 28)
                    | ((u.x & 0x00000F00u) << 16)
                    | ((u.x & 0x000F0000u) << 4)
                    | ((u.x & 0x0F000000u) >> 8);
        uint32_t lo = ((u.y & 0x0000000Fu) << 12)
                    | ((u.y & 0x00000F00u) >> 0)
                    | ((u.y & 0x000F0000u) >> 12)
                    | ((u.y & 0x0F000000u) >> 24);
        uint32_t packed = hi | lo;

        float4 o0, o1;
        convert_row(packed, o0, o1);

        const int row = baserow + lane;
        __stcs(&out[(size_t)row * 2],     o0);
        __stcs(&out[(size_t)row * 2 + 1], o1);
    } else {
        // ---- tail path: per-thread row ----
        const int row = baserow + lane;
        if (row >= nrows) return;
        const uint4* p = in + (size_t)row * 8;
        uint32_t packed = 0;
#pragma unroll
        for (int k = 0; k < 8; k++)
            packed = (packed << 4) | nibble_of(__ldcs(&p[k]));
        float4 o0, o1;
        convert_row(packed, o0, o1);
        __stcs(&out[(size_t)row * 2],     o0);
        __stcs(&out[(size_t)row * 2 + 1], o1);
    }
}

extern "C" void kernel_launch(void* const* d_in, const int* in_sizes, int n_in,
                              void* d_out, int out_size)
{
    const uint4* in = (const uint4*)d_in[0];
    float4* out = (float4*)d_out;
    int nrows = in_sizes[0] / 32;

    int threads = 256;
    int blocks = (nrows + threads - 1) / threads;
    fp32_to_fp8_pulse_kernel<<<blocks, threads>>>(in, out, nrows);
}

// round 12
// speedup vs baseline: 1.0056x; 1.0056x over previous
#include <cuda_runtime.h>
#include <stdint.h>

// FP32 bit-pulse -> FP8 E4M3 bit-pulse converter — FINAL (R5 config).
// Input : N*32 floats (0.0f/1.0f), row = [S, E7..E0, M22..M0] MSB first
// Output: N*8  floats, row = [S, E3..E0, M2..M0]
//
// Warp-cooperative smem nibble transpose:
//  - warp owns 32 consecutive rows (4KB contiguous input)
//  - 8 coalesced LDG.128 (__ldcs) passes; each lane reduces its uint4 to a
//    4-bit nibble (bit 29 of 1.0f) byte-stored at smem[p*32+lane], which is
//    row-major nibble order by construction
//  - lane r reads its row's 8 nibble-bytes with one conflict-free LDS.64,
//    packs into the IEEE754 word, does the bit-exact RNE E4M3 conversion,
//    stores 2x STG.128 (__stcs)
//
// Session conclusion (9 variants measured): harness steady state is pinned
// at 51.2-52.0us = 320MB irreducible traffic at ~6.2TB/s sustained HBM +
// fixed replay overhead. DRAM 80-85% with all other pipes <=33%; no lever
// (MLP batching, persistence, pipelining, any L2 policy, shorter store
// chain) moved it. This kernel is at the GB300 mixed-stream HBM floor.

__device__ __forceinline__ void convert_row(uint32_t packed,
                                            float4& o0, float4& o1)
{
    uint32_t s    = packed >> 31;
    uint32_t exp  = (packed >> 23) & 0xFFu;
    uint32_t mant = packed & 0x7FFFFFu;

    // normal path: RNE round 23 -> 3 mantissa bits
    uint32_t kept = mant >> 20;
    uint32_t R    = (mant >> 19) & 1u;
    uint32_t S    = (mant & ((1u << 19) - 1u)) != 0u;
    uint32_t L    = kept & 1u;
    uint32_t mr   = kept + (R & (S | L));
    uint32_t carry = mr >> 3;
    uint32_t mant_norm = carry ? 0u : (mr & 7u);
    uint32_t exp_norm  = exp - 120u + carry;

    // subnormal path (117 <= exp <= 120)
    uint32_t full = (1u << 23) | mant;
    int shi = 141 - (int)exp;
    if (shi < 1)  shi = 1;
    if (shi > 24) shi = 24;
    uint32_t sh = (uint32_t)shi;
    uint32_t kept_s = full >> sh;
    uint32_t Rs = (full >> (sh - 1u)) & 1u;
    uint32_t Ss = (full & ((1u << (sh - 1u)) - 1u)) != 0u;
    uint32_t Ls = kept_s & 1u;
    uint32_t ms = kept_s + (Rs & (Ss | Ls));
    uint32_t sub_exp  = (ms >= 8u) ? 1u : 0u;
    uint32_t sub_mant = (ms >= 8u) ? 0u : ms;

    uint32_t exp8, mant8;
    if (exp > 134u)                      { exp8 = 15u;      mant8 = 6u;        }
    else if (exp >= 117u && exp <= 120u) { exp8 = sub_exp;  mant8 = sub_mant;  }
    else if (exp < 117u)                 { exp8 = 0u;       mant8 = 0u;        }
    else                                 { exp8 = exp_norm; mant8 = mant_norm; }

    o0.x = (float)s;
    o0.y = (float)((exp8 >> 3) & 1u);
    o0.z = (float)((exp8 >> 2) & 1u);
    o0.w = (float)((exp8 >> 1) & 1u);
    o1.x = (float)(exp8 & 1u);
    o1.y = (float)((mant8 >> 2) & 1u);
    o1.z = (float)((mant8 >> 1) & 1u);
    o1.w = (float)(mant8 & 1u);
}

__device__ __forceinline__ uint32_t nibble_of(uint4 v)
{
    return (((v.x >> 29) & 1u) << 3)
         | (((v.y >> 29) & 1u) << 2)
         | (((v.z >> 29) & 1u) << 1)
         |  ((v.w >> 29) & 1u);
}

__global__ __launch_bounds__(256) void fp32_to_fp8_pulse_kernel(
    const uint4* __restrict__ in,   // 8 x uint4 per row
    float4* __restrict__ out,       // 2 x float4 per row
    int nrows)
{
    __shared__ uint8_t snib[8][256];   // per-warp: 32 rows x 8 nibble-bytes

    const int warp = threadIdx.x >> 5;
    const int lane = threadIdx.x & 31;
    const int baserow = (blockIdx.x * 8 + warp) * 32;
    if (baserow >= nrows) return;

    if (baserow + 32 <= nrows) {
        // ---- fast path: full 32-row tile ----
        const uint4* tile = in + (size_t)baserow * 8;

        // coalesced streaming loads; each lane stores one nibble-byte per pass.
#pragma unroll
        for (int p = 0; p < 8; p++) {
            uint4 v = __ldcs(&tile[p * 32 + lane]);
            snib[warp][p * 32 + lane] = (uint8_t)nibble_of(v);
        }
        __syncwarp();

        // lane r: one LDS.64 fetches row r's 8 nibbles (bytes 8r..8r+7)
        uint2 u = *reinterpret_cast<const uint2*>(&snib[warp][lane * 8]);

        uint32_t hi = ((u.x & 0x0000000Fu) << 28)
                    | ((u.x & 0x00000F00u) << 16)
                    | ((u.x & 0x000F0000u) << 4)
                    | ((u.x & 0x0F000000u) >> 8);
        uint32_t lo = ((u.y & 0x0000000Fu) << 12)
                    | ((u.y & 0x00000F00u) >> 0)
                    | ((u.y & 0x000F0000u) >> 12)
                    | ((u.y & 0x0F000000u) >> 24);
        uint32_t packed = hi | lo;

        float4 o0, o1;
        convert_row(packed, o0, o1);

        const int row = baserow + lane;
        __stcs(&out[(size_t)row * 2],     o0);
        __stcs(&out[(size_t)row * 2 + 1], o1);
    } else {
        // ---- tail path: per-thread row ----
        const int row = baserow + lane;
        if (row >= nrows) return;
        const uint4* p = in + (size_t)row * 8;
        uint32_t packed = 0;
#pragma unroll
        for (int k = 0; k < 8; k++)
            packed = (packed << 4) | nibble_of(__ldcs(&p[k]));
        float4 o0, o1;
        convert_row(packed, o0, o1);
        __stcs(&out[(size_t)row * 2],     o0);
        __stcs(&out[(size_t)row * 2 + 1], o1);
    }
}

extern "C" void kernel_launch(void* const* d_in, const int* in_sizes, int n_in,
                              void* d_out, int out_size)
{
    const uint4* in = (const uint4*)d_in[0];
    float4* out = (float4*)d_out;
    int nrows = in_sizes[0] / 32;

    int threads = 256;
    int blocks = (nrows + threads - 1) / threads;
    fp32_to_fp8_pulse_kernel<<<blocks, threads>>>(in, out, nrows);
}

// round 15
// speedup vs baseline: 1.0131x; 1.0075x over previous
#include <cuda_runtime.h>
#include <stdint.h>

// FP32 bit-pulse -> FP8 E4M3 bit-pulse converter.
// Input : N*32 floats (0.0f/1.0f), row = [S, E7..E0, M22..M0] MSB first
// Output: N*8  floats, row = [S, E3..E0, M2..M0]
//
// R5 structure (warp-cooperative smem nibble transpose, __ldcs loads) plus
// smem-staged COALESCED stores: instead of each lane issuing 2 STG.128 at
// 32B stride (1KB span, 8 half-filled lines per instruction), lanes stage
// their o0/o1 into the reused 2KB smem tile and the warp emits 2 perfectly
// coalesced passes (512B contiguous per STG.128, 4 full lines). Halves
// store-side L1 wavefronts; DRAM traffic unchanged.

__device__ __forceinline__ void convert_row(uint32_t packed,
                                            float4& o0, float4& o1)
{
    uint32_t s    = packed >> 31;
    uint32_t exp  = (packed >> 23) & 0xFFu;
    uint32_t mant = packed & 0x7FFFFFu;

    // normal path: RNE round 23 -> 3 mantissa bits
    uint32_t kept = mant >> 20;
    uint32_t R    = (mant >> 19) & 1u;
    uint32_t S    = (mant & ((1u << 19) - 1u)) != 0u;
    uint32_t L    = kept & 1u;
    uint32_t mr   = kept + (R & (S | L));
    uint32_t carry = mr >> 3;
    uint32_t mant_norm = carry ? 0u : (mr & 7u);
    uint32_t exp_norm  = exp - 120u + carry;

    // subnormal path (117 <= exp <= 120)
    uint32_t full = (1u << 23) | mant;
    int shi = 141 - (int)exp;
    if (shi < 1)  shi = 1;
    if (shi > 24) shi = 24;
    uint32_t sh = (uint32_t)shi;
    uint32_t kept_s = full >> sh;
    uint32_t Rs = (full >> (sh - 1u)) & 1u;
    uint32_t Ss = (full & ((1u << (sh - 1u)) - 1u)) != 0u;
    uint32_t Ls = kept_s & 1u;
    uint32_t ms = kept_s + (Rs & (Ss | Ls));
    uint32_t sub_exp  = (ms >= 8u) ? 1u : 0u;
    uint32_t sub_mant = (ms >= 8u) ? 0u : ms;

    uint32_t exp8, mant8;
    if (exp > 134u)                      { exp8 = 15u;      mant8 = 6u;        }
    else if (exp >= 117u && exp <= 120u) { exp8 = sub_exp;  mant8 = sub_mant;  }
    else if (exp < 117u)                 { exp8 = 0u;       mant8 = 0u;        }
    else                                 { exp8 = exp_norm; mant8 = mant_norm; }

    o0.x = (float)s;
    o0.y = (float)((exp8 >> 3) & 1u);
    o0.z = (float)((exp8 >> 2) & 1u);
    o0.w = (float)((exp8 >> 1) & 1u);
    o1.x = (float)(exp8 & 1u);
    o1.y = (float)((mant8 >> 2) & 1u);
    o1.z = (float)((mant8 >> 1) & 1u);
    o1.w = (float)(mant8 & 1u);
}

__device__ __forceinline__ uint32_t nibble_of(uint4 v)
{
    return (((v.x >> 29) & 1u) << 3)
         | (((v.y >> 29) & 1u) << 2)
         | (((v.z >> 29) & 1u) << 1)
         |  ((v.w >> 29) & 1u);
}

__global__ __launch_bounds__(256) void fp32_to_fp8_pulse_kernel(
    const uint4* __restrict__ in,   // 8 x uint4 per row
    float4* __restrict__ out,       // 2 x float4 per row
    int nrows)
{
    // per-warp 2KB buffer, reused: phase 1 = 256 nibble-bytes,
    // phase 2 = 64 float4 of staged output (32 rows x 2 float4).
    __shared__ __align__(16) uint8_t sbuf[8][2048];

    const int warp = threadIdx.x >> 5;
    const int lane = threadIdx.x & 31;
    const int baserow = (blockIdx.x * 8 + warp) * 32;
    if (baserow >= nrows) return;

    if (baserow + 32 <= nrows) {
        // ---- phase 1: coalesced streaming loads -> nibble bytes ----
        const uint4* tile = in + (size_t)baserow * 8;
#pragma unroll
        for (int p = 0; p < 8; p++) {
            uint4 v = __ldcs(&tile[p * 32 + lane]);
            sbuf[warp][p * 32 + lane] = (uint8_t)nibble_of(v);
        }
        __syncwarp();

        // lane r: one LDS.64 fetches row r's 8 nibbles (bytes 8r..8r+7)
        uint2 u = *reinterpret_cast<const uint2*>(&sbuf[warp][lane * 8]);

        uint32_t hi = ((u.x & 0x0000000Fu) << 28)
                    | ((u.x & 0x00000F00u) << 16)
                    | ((u.x & 0x000F0000u) << 4)
                    | ((u.x & 0x0F000000u) >> 8);
        uint32_t lo = ((u.y & 0x0000000Fu) << 12)
                    | ((u.y & 0x00000F00u) >> 0)
                    | ((u.y & 0x000F0000u) >> 12)
                    | ((u.y & 0x0F000000u) >> 24);
        uint32_t packed = hi | lo;

        float4 o0, o1;
        convert_row(packed, o0, o1);

        // ---- phase 2: stage output in smem, then coalesced stores ----
        float4* sout = reinterpret_cast<float4*>(sbuf[warp]);
        __syncwarp();                 // nibble reads done before overwrite
        sout[lane * 2]     = o0;      // row-major: float4 idx 2r, 2r+1
        sout[lane * 2 + 1] = o1;
        __syncwarp();

        float4* obase = out + (size_t)baserow * 2;   // 64 float4, contiguous
        __stcs(&obase[lane],      sout[lane]);       // 512B contiguous
        __stcs(&obase[32 + lane], sout[32 + lane]);  // 512B contiguous
    } else {
        // ---- tail path: per-thread row ----
        const int row = baserow + lane;
        if (row >= nrows) return;
        const uint4* p = in + (size_t)row * 8;
        uint32_t packed = 0;
#pragma unroll
        for (int k = 0; k < 8; k++)
            packed = (packed << 4) | nibble_of(__ldcs(&p[k]));
        float4 o0, o1;
        convert_row(packed, o0, o1);
        __stcs(&out[(size_t)row * 2],     o0);
        __stcs(&out[(size_t)row * 2 + 1], o1);
    }
}

extern "C" void kernel_launch(void* const* d_in, const int* in_sizes, int n_in,
                              void* d_out, int out_size)
{
    const uint4* in = (const uint4*)d_in[0];
    float4* out = (float4*)d_out;
    int nrows = in_sizes[0] / 32;

    int threads = 256;
    int blocks = (nrows + threads - 1) / threads;
    fp32_to_fp8_pulse_kernel<<<blocks, threads>>>(in, out, nrows);
}